// round 7
// baseline (speedup 1.0000x reference)
#include <cuda_runtime.h>

#define NT 128
#define ST 72   // 72 ≡ 8 (mod 32): with col^=(row&4) swizzle all frag accesses are conflict-free

__device__ __forceinline__ float f2tf(float x) {
    unsigned r;
    asm("cvt.rna.tf32.f32 %0, %1;" : "=r"(r) : "f"(x));
    return __uint_as_float(r);
}

__device__ __forceinline__ void mma8(float* c, unsigned a0, unsigned a1, unsigned a2, unsigned a3,
                                     unsigned b0, unsigned b1) {
    asm("mma.sync.aligned.m16n8k8.row.col.f32.tf32.tf32.f32 "
        "{%0,%1,%2,%3}, {%4,%5,%6,%7}, {%8,%9}, {%0,%1,%2,%3};"
        : "+f"(c[0]), "+f"(c[1]), "+f"(c[2]), "+f"(c[3])
        : "r"(a0), "r"(a1), "r"(a2), "r"(a3), "r"(b0), "r"(b1));
}

// C(16w..16w+15, 0..63) += A(rows from smem, swizzled) @ B(smem, swizzled)
__device__ __forceinline__ void gemm_ss(const float* __restrict__ A, const float* __restrict__ B,
                                        int rb, int gid, int tig, float c[8][4]) {
#pragma unroll
    for (int nt = 0; nt < 8; nt++)
#pragma unroll
        for (int q = 0; q < 4; q++) c[nt][q] = 0.0f;

    const int x4 = gid & 4;
    const int ca = tig ^ x4;
    const float* A0 = A + (rb + gid) * ST;
    const float* A1 = A0 + 8 * ST;
    const float* B0 = B + tig * ST;           // b0 rows: bit2=0, no col xor
    const float* B1 = B + (tig + 4) * ST;     // b1 rows: bit2=1, col^4
    const int g0 = gid, g1 = gid ^ 4;
#pragma unroll
    for (int ks = 0; ks < 8; ks++) {
        unsigned a0 = __float_as_uint(A0[ca + 8 * ks]);
        unsigned a1 = __float_as_uint(A1[ca + 8 * ks]);
        unsigned a2 = __float_as_uint(A0[(ca ^ 4) + 8 * ks]);
        unsigned a3 = __float_as_uint(A1[(ca ^ 4) + 8 * ks]);
        const float* b0r = B0 + 8 * ks * ST;
        const float* b1r = B1 + 8 * ks * ST;
#pragma unroll
        for (int nt = 0; nt < 8; nt++) {
            unsigned b0 = __float_as_uint(b0r[g0 + 8 * nt]);
            unsigned b1 = __float_as_uint(b1r[g1 + 8 * nt]);
            mma8(c[nt], a0, a1, a2, a3, b0, b1);
        }
    }
}

// Same but A-fragments live in registers (binary adjacency, cached once).
__device__ __forceinline__ void gemm_rs(const unsigned af[8][4], const float* __restrict__ B,
                                        int gid, int tig, float c[8][4]) {
#pragma unroll
    for (int nt = 0; nt < 8; nt++)
#pragma unroll
        for (int q = 0; q < 4; q++) c[nt][q] = 0.0f;

    const float* B0 = B + tig * ST;
    const float* B1 = B + (tig + 4) * ST;
    const int g0 = gid, g1 = gid ^ 4;
#pragma unroll
    for (int ks = 0; ks < 8; ks++) {
        const float* b0r = B0 + 8 * ks * ST;
        const float* b1r = B1 + 8 * ks * ST;
#pragma unroll
        for (int nt = 0; nt < 8; nt++) {
            unsigned b0 = __float_as_uint(b0r[g0 + 8 * nt]);
            unsigned b1 = __float_as_uint(b1r[g1 + 8 * nt]);
            mma8(c[nt], af[ks][0], af[ks][1], af[ks][2], af[ks][3], b0, b1);
        }
    }
}

// Stage a 64x64 weight block (row stride `stride`, col offset coff) into swizzled tf32 smem.
__device__ __forceinline__ void stage_w(float* dst, const float* __restrict__ src,
                                        int stride, int coff, int tid) {
    for (int idx = tid; idx < 1024; idx += NT) {
        int k = idx >> 4, jc = (idx & 15) << 2;
        float4 v = *(const float4*)(src + k * stride + coff + jc);
        v.x = f2tf(v.x); v.y = f2tf(v.y); v.z = f2tf(v.z); v.w = f2tf(v.w);
        *(float4*)&dst[k * ST + (jc ^ (k & 4))] = v;
    }
}

__global__ __launch_bounds__(NT, 4) void pgcn_kernel(
    const float* __restrict__ device_obs,   // [B,63,14]
    const float* __restrict__ server_obs,   // [B,3]
    const float* __restrict__ adjacency,    // [B,64,64] binary
    const float* __restrict__ W_dev, const float* __restrict__ b_dev,
    const float* __restrict__ W_srv, const float* __restrict__ b_srv,
    const float* __restrict__ W1, const float* __restrict__ b1,
    const float* __restrict__ W2, const float* __restrict__ b2,
    const float* __restrict__ W3, const float* __restrict__ b3,
    const float* __restrict__ Wf1, const float* __restrict__ bf1,
    const float* __restrict__ Wf2, const float* __restrict__ bf2,
    float* __restrict__ out)                // [B,63]
{
    extern __shared__ float sm[];
    float* s_h    = sm;                 // [64][ST] activations; row tails 64..66 hold b1,b2,b3
    float* s_w    = sm + 4608;          // [64][ST] staged weights (initially embed staging)
    float* s_aux  = sm + 9216;          // [64][ST] adjacency; later Wf1 chunk1
    float* s_d    = sm + 13824;         // 64
    float* s_mean = s_d + 64;           // 64
    float* s_sh   = s_mean + 64;        // 128
    float* s_w2   = s_sh + 128;         // 128

    const int b    = blockIdx.x;
    const int tid  = threadIdx.x;
    const int w    = tid >> 5;
    const int lane = tid & 31;
    const int gid  = lane >> 2;
    const int tig  = lane & 3;
    const int rb   = w << 4;
    const int r0   = rb + gid, r1 = r0 + 8;
    const int x4   = gid & 4;

    // ---- P0: stage everything ----
    {
        const float4* adjg = (const float4*)(adjacency + (size_t)b * 4096);
#pragma unroll
        for (int idx = tid; idx < 1024; idx += NT) {
            int row = idx >> 4, jc = (idx & 15) << 2;
            *(float4*)&s_aux[row * ST + (jc ^ (row & 4))] = adjg[idx];   // binary, tf32-exact
        }
        const float* dob = device_obs + (size_t)b * 882;
        for (int idx = tid; idx < 882; idx += NT) s_w[idx] = dob[idx];
        for (int idx = tid; idx < 896; idx += NT) s_w[896 + idx] = W_dev[idx];
        if (tid < 64) s_w[1792 + tid] = b_dev[tid];
        for (int idx = tid; idx < 192; idx += NT) s_w[1856 + idx] = W_srv[idx];
        if (tid < 64) s_w[2048 + tid] = b_srv[tid];
        if (tid < 64) {           // biases in s_h row tails (cols 64..66, never clobbered)
            s_h[tid * ST + 64] = b1[tid];
            s_h[tid * ST + 65] = b2[tid];
            s_h[tid * ST + 66] = b3[tid];
        }
        if (tid < 128) s_w2[tid] = Wf2[tid];
    }
    const float so0 = server_obs[b * 3 + 0];
    const float so1 = server_obs[b * 3 + 1];
    const float so2 = server_obs[b * 3 + 2];
    const float bf2v = bf2[0];
    __syncthreads();

    // ---- degree -> d^-1/2 (row sum invariant under col permutation) ----
    if (tid < 64) {
        float s = 0.0f;
#pragma unroll
        for (int jc = 0; jc < 16; jc++) {
            float4 v = *(const float4*)&s_aux[tid * ST + (jc << 2)];
            s += (v.x + v.y) + (v.z + v.w);
        }
        s_d[tid] = rsqrtf(fmaxf(s, 1.0f));
    }
    __syncthreads();

    // ---- embed: x -> s_h (tf32, swizzled) ----
    {
        const float* s_obs  = s_w;
        const float* s_wdev = s_w + 896;
        const float* s_bdev = s_w + 1792;
        const float* s_wsrv = s_w + 1856;
        const float* s_bsrv = s_w + 2048;
        for (int idx = tid; idx < 4096; idx += NT) {
            int i = idx >> 6, j = idx & 63;
            float acc;
            if (i < 63) {
                acc = s_bdev[j];
                const float* o = s_obs + i * 14;
#pragma unroll
                for (int k = 0; k < 14; k++)
                    acc = fmaf(o[k], s_wdev[k * 64 + j], acc);
            } else {
                acc = s_bsrv[j];
                acc = fmaf(so0, s_wsrv[j], acc);
                acc = fmaf(so1, s_wsrv[64 + j], acc);
                acc = fmaf(so2, s_wsrv[128 + j], acc);
            }
            s_h[i * ST + (j ^ (i & 4))] = f2tf(fmaxf(acc, 0.0f));
        }
    }
    __syncthreads();

    // ---- cache adjacency A-fragments in registers; stage W1 ----
    unsigned af[8][4];
    {
        const float* A0 = s_aux + r0 * ST;
        const float* A1 = s_aux + r1 * ST;
        const int ca = tig ^ x4;
#pragma unroll
        for (int ks = 0; ks < 8; ks++) {
            af[ks][0] = __float_as_uint(A0[ca + 8 * ks]);
            af[ks][1] = __float_as_uint(A1[ca + 8 * ks]);
            af[ks][2] = __float_as_uint(A0[(ca ^ 4) + 8 * ks]);
            af[ks][3] = __float_as_uint(A1[(ca ^ 4) + 8 * ks]);
        }
    }
    stage_w(s_w, W1, 64, 0, tid);
    __syncthreads();

    const float dr0 = s_d[r0], dr1 = s_d[r1];
    const int pc0 = 2 * tig;   // logical col base of C frags

    // ---- 3 GCN layers: h' = relu(D·A·(D·(h@W)) + b) ----
    const float* stage_src[3] = {W2, W3, Wf1};
    const int    stage_str[3] = {64, 64, 128};
#pragma unroll 1
    for (int L = 0; L < 3; L++) {
        float c[8][4];
        // GEMM-A: g = h @ W_L (A = own rows of s_h)
        gemm_ss(s_h, s_w, rb, gid, tig, c);
        // epilogue: g' = d_k * g, tf32, into own rows of s_h (warp-private, no race)
#pragma unroll
        for (int nt = 0; nt < 8; nt++) {
            int pc = ((nt << 3) + pc0) ^ x4;
            *(float2*)&s_h[r0 * ST + pc] = make_float2(f2tf(c[nt][0] * dr0), f2tf(c[nt][1] * dr0));
            *(float2*)&s_h[r1 * ST + pc] = make_float2(f2tf(c[nt][2] * dr1), f2tf(c[nt][3] * dr1));
        }
        __syncthreads();   // g' visible; all s_w reads done

        // GEMM-B: C2 = A(binary, regs) @ g' ; concurrently stage next weights
        gemm_rs(af, s_h, gid, tig, c);
        stage_w(s_w, stage_src[L], stage_str[L], 0, tid);
        __syncthreads();   // all g' reads done; next W visible

        // epilogue: h' = relu(d_i*C2 + b_L), tf32, own rows
#pragma unroll
        for (int nt = 0; nt < 8; nt++) {
            int j = (nt << 3) + pc0;
            float bx = s_h[j * ST + 64 + L];
            float by = s_h[(j + 1) * ST + 64 + L];
            int pc = j ^ x4;
            *(float2*)&s_h[r0 * ST + pc] =
                make_float2(f2tf(fmaxf(fmaf(dr0, c[nt][0], bx), 0.0f)),
                            f2tf(fmaxf(fmaf(dr0, c[nt][1], by), 0.0f)));
            *(float2*)&s_h[r1 * ST + pc] =
                make_float2(f2tf(fmaxf(fmaf(dr1, c[nt][2], bx), 0.0f)),
                            f2tf(fmaxf(fmaf(dr1, c[nt][3], by), 0.0f)));
        }
        __syncwarp();      // own rows re-read by same warp's next GEMM-A
    }
    __syncthreads();       // full h needed by mean / head B-reads

    // ---- dev_mean; stage Wf1 chunk1 into s_aux ----
    if (tid < 64) {
        float s = 0.0f;
#pragma unroll 7
        for (int r = 0; r < 63; r++) s += s_h[r * ST + (tid ^ (r & 4))];
        s_mean[tid] = s * (1.0f / 63.0f);
    }
    stage_w(s_aux, Wf1, 128, 64, tid);
    __syncthreads();

    // ---- shared head vector: bf1 + mean@Wf1[64:128] + srv@Wf1[128:192] ----
    {
        float acc = bf1[tid];
#pragma unroll 4
        for (int k = 0; k < 64; k++) {
            float srv = s_h[63 * ST + (k ^ 4)];
            acc = fmaf(s_mean[k], Wf1[(64 + k) * 128 + tid], acc);
            acc = fmaf(srv,       Wf1[(128 + k) * 128 + tid], acc);
        }
        s_sh[tid] = acc;
    }
    __syncthreads();

    // ---- head: two 64-col chunks, fully register-resident epilogue ----
    float p0 = 0.0f, p1 = 0.0f;
#pragma unroll 1
    for (int c2 = 0; c2 < 2; c2++) {
        float c[8][4];
        gemm_ss(s_h, (c2 ? s_aux : s_w), rb, gid, tig, c);
#pragma unroll
        for (int nt = 0; nt < 8; nt++) {
            int col = (c2 << 6) + (nt << 3) + pc0;
            float2 sh = *(const float2*)&s_sh[col];
            float2 w2 = *(const float2*)&s_w2[col];
            p0 = fmaf(fmaxf(c[nt][0] + sh.x, 0.0f), w2.x, p0);
            p0 = fmaf(fmaxf(c[nt][1] + sh.y, 0.0f), w2.y, p0);
            p1 = fmaf(fmaxf(c[nt][2] + sh.x, 0.0f), w2.x, p1);
            p1 = fmaf(fmaxf(c[nt][3] + sh.y, 0.0f), w2.y, p1);
        }
    }

    p0 += __shfl_xor_sync(0xffffffffu, p0, 1, 4);
    p0 += __shfl_xor_sync(0xffffffffu, p0, 2, 4);
    p1 += __shfl_xor_sync(0xffffffffu, p1, 1, 4);
    p1 += __shfl_xor_sync(0xffffffffu, p1, 2, 4);
    if (tig == 0) {
        out[(size_t)b * 63 + r0] = p0 + bf2v;
        if (r1 < 63) out[(size_t)b * 63 + r1] = p1 + bf2v;
    }
}

extern "C" void kernel_launch(void* const* d_in, const int* in_sizes, int n_in,
                              void* d_out, int out_size)
{
    const float* device_obs = (const float*)d_in[0];
    const float* server_obs = (const float*)d_in[1];
    const float* adjacency  = (const float*)d_in[2];
    const float* W_dev = (const float*)d_in[3];
    const float* b_dev = (const float*)d_in[4];
    const float* W_srv = (const float*)d_in[5];
    const float* b_srv = (const float*)d_in[6];
    const float* W1 = (const float*)d_in[7];
    const float* b1 = (const float*)d_in[8];
    const float* W2 = (const float*)d_in[9];
    const float* b2 = (const float*)d_in[10];
    const float* W3 = (const float*)d_in[11];
    const float* b3 = (const float*)d_in[12];
    const float* Wf1 = (const float*)d_in[13];
    const float* bf1 = (const float*)d_in[14];
    const float* Wf2 = (const float*)d_in[15];
    const float* bf2 = (const float*)d_in[16];

    const int B = in_sizes[0] / (63 * 14);
    const size_t smem = (3 * 64 * ST + 64 + 64 + 128 + 128) * sizeof(float);
    cudaFuncSetAttribute(pgcn_kernel, cudaFuncAttributeMaxDynamicSharedMemorySize, (int)smem);
    pgcn_kernel<<<B, NT, smem>>>(
        device_obs, server_obs, adjacency,
        W_dev, b_dev, W_srv, b_srv,
        W1, b1, W2, b2, W3, b3,
        Wf1, bf1, Wf2, bf2,
        (float*)d_out);
}